// round 1
// baseline (speedup 1.0000x reference)
#include <cuda_runtime.h>

#define Sdim 4096
#define Ddim 64
#define WIN  256
#define Hn   16
#define TQ   32
#define CK   64
#define NCH  9
#define KBUF (CK*NCH)   /* 576 */
#define SROW 580
#define QROW 34

// SMEM floats: scores[TQ][SROW] + Qs[D][QROW] + KVs[CK][D] + invs[TQ]
#define SMEM_FLOATS (TQ*SROW + Ddim*QROW + CK*Ddim + TQ)

__global__ __launch_bounds__(256, 2)
void swa_kernel(const float* __restrict__ Q, const float* __restrict__ K,
                const float* __restrict__ V, float* __restrict__ outp,
                float* __restrict__ attn)
{
    extern __shared__ float sm[];
    float* scores = sm;                     // [TQ][SROW]
    float* Qs     = sm + TQ*SROW;           // [D][QROW]  (d-major)
    float* KVs    = Qs + Ddim*QROW;         // [CK][D] or [D][CK]
    float* invs   = KVs + CK*Ddim;          // [TQ]

    const int h    = blockIdx.y;
    const int qb   = blockIdx.x * TQ;
    const int tid  = threadIdx.x;
    const int koff = qb - WIN;              // buffer covers keys [koff, koff+576)

    // ---- Load Q tile (32x64), store transposed d-major ----
    {
        const float4* Q4 = (const float4*)(Q + (size_t)(h*Sdim + qb)*Ddim);
        #pragma unroll
        for (int i = 0; i < 2; i++) {
            int idx = tid + 256*i;      // 512 float4 total
            int q  = idx >> 4;
            int dg = idx & 15;
            float4 v = Q4[q*16 + dg];
            Qs[(4*dg+0)*QROW + q] = v.x;
            Qs[(4*dg+1)*QROW + q] = v.y;
            Qs[(4*dg+2)*QROW + q] = v.z;
            Qs[(4*dg+3)*QROW + q] = v.w;
        }
    }
    __syncthreads();

    const int tq = tid & 15;    // 16 query-pairs / 16 query-splits
    const int tk = tid >> 4;    // 16 groups of 4 keys / 4 dims

    // ======== GEMM1: scores = Q K^T * 0.125, banded mask -> -1e9 ========
    for (int c = 0; c < NCH; c++) {
        const int kc = koff + c*CK;
        const bool any = (kc < Sdim) && (kc + CK > 0);   // uniform per block
        if (any) {
            // load K chunk transposed: KVs[d][k], stride CK
            #pragma unroll
            for (int i = 0; i < 4; i++) {
                int idx = tid + 256*i;   // 1024 float4
                int kk = idx >> 4;
                int dg = idx & 15;
                int kg = kc + kk;
                float4 v = make_float4(0.f,0.f,0.f,0.f);
                if (kg >= 0 && kg < Sdim)
                    v = *(const float4*)(K + (size_t)(h*Sdim + kg)*Ddim + 4*dg);
                KVs[(4*dg+0)*CK + kk] = v.x;
                KVs[(4*dg+1)*CK + kk] = v.y;
                KVs[(4*dg+2)*CK + kk] = v.z;
                KVs[(4*dg+3)*CK + kk] = v.w;
            }
            __syncthreads();

            float acc[2][4] = {};
            #pragma unroll 8
            for (int d = 0; d < Ddim; d++) {
                float2 qv = *(const float2*)&Qs[d*QROW + 2*tq];
                float4 kv = *(const float4*)&KVs[d*CK + 4*tk];
                acc[0][0] += qv.x*kv.x; acc[0][1] += qv.x*kv.y;
                acc[0][2] += qv.x*kv.z; acc[0][3] += qv.x*kv.w;
                acc[1][0] += qv.y*kv.x; acc[1][1] += qv.y*kv.y;
                acc[1][2] += qv.y*kv.z; acc[1][3] += qv.y*kv.w;
            }
            #pragma unroll
            for (int j = 0; j < 2; j++) {
                int q  = 2*tq + j;
                int qg = qb + q;
                int k0 = kc + 4*tk;
                float4 r;
                float* rp = &r.x;
                #pragma unroll
                for (int i = 0; i < 4; i++) {
                    int kg = k0 + i;
                    bool ok = (kg >= 0) && (kg < Sdim) &&
                              ((unsigned)(kg - qg + WIN) <= 2u*WIN);
                    rp[i] = ok ? acc[j][i]*0.125f : -1e9f;
                }
                *(float4*)&scores[q*SROW + c*CK + 4*tk] = r;
            }
            __syncthreads();   // KVs reused next chunk
        } else {
            float4 mneg = make_float4(-1e9f,-1e9f,-1e9f,-1e9f);
            *(float4*)&scores[(2*tq  )*SROW + c*CK + 4*tk] = mneg;
            *(float4*)&scores[(2*tq+1)*SROW + c*CK + 4*tk] = mneg;
        }
    }
    __syncthreads();

    // ======== softmax per query row (warp handles 4 rows) ========
    {
        const int warp = tid >> 5, lane = tid & 31;
        for (int qq = 0; qq < 4; qq++) {
            int q = warp*4 + qq;
            float* row = scores + q*SROW;
            float m = -3.0e38f;
            for (int i = lane; i < KBUF; i += 32) m = fmaxf(m, row[i]);
            #pragma unroll
            for (int o = 16; o > 0; o >>= 1) m = fmaxf(m, __shfl_xor_sync(0xffffffffu, m, o));
            float ssum = 0.f;
            for (int i = lane; i < KBUF; i += 32) {
                float p = __expf(row[i] - m);   // masked -1e9 underflows to exact 0
                row[i] = p;
                ssum += p;
            }
            #pragma unroll
            for (int o = 16; o > 0; o >>= 1) ssum += __shfl_xor_sync(0xffffffffu, ssum, o);
            if (lane == 0) invs[q] = 1.0f / ssum;
        }
    }
    __syncthreads();

    // ======== write dense attn rows (zeros outside buffer/band) ========
    {
        float* arow = attn + (size_t)(h*Sdim + qb)*Sdim;
        for (int idx = tid; idx < TQ*(Sdim/4); idx += 256) {
            int q  = idx >> 10;            // Sdim/4 = 1024 groups per row
            int g  = idx & 1023;
            int k0 = g*4;
            int b  = k0 - koff;
            float4 v;
            if (b >= 0 && b < KBUF) {
                float4 p = *(float4*)&scores[q*SROW + b];
                float is = invs[q];
                v = make_float4(p.x*is, p.y*is, p.z*is, p.w*is);
            } else {
                v = make_float4(0.f,0.f,0.f,0.f);
            }
            *(float4*)&arow[(size_t)q*Sdim + k0] = v;
        }
    }

    // ======== GEMM2: out = P V (P = unnormalized exp, scale at end) ========
    float acc[2][4] = {};
    for (int c = 0; c < NCH; c++) {
        const int kc = koff + c*CK;
        if (kc >= Sdim || kc + CK <= 0) continue;   // uniform
        // load V chunk (k-major, stride D)
        #pragma unroll
        for (int i = 0; i < 4; i++) {
            int idx = tid + 256*i;
            int kk = idx >> 4;
            int dg = idx & 15;
            int kg = kc + kk;
            float4 v = make_float4(0.f,0.f,0.f,0.f);
            if (kg >= 0 && kg < Sdim)
                v = *(const float4*)(V + (size_t)(h*Sdim + kg)*Ddim + 4*dg);
            *(float4*)&KVs[kk*Ddim + 4*dg] = v;
        }
        __syncthreads();

        const int cb = c*CK;
        #pragma unroll 8
        for (int kk = 0; kk < CK; kk++) {
            float pa = scores[(tq     )*SROW + cb + kk];
            float pb = scores[(tq + 16)*SROW + cb + kk];
            float4 vv = *(const float4*)&KVs[kk*Ddim + 4*tk];
            acc[0][0] += pa*vv.x; acc[0][1] += pa*vv.y;
            acc[0][2] += pa*vv.z; acc[0][3] += pa*vv.w;
            acc[1][0] += pb*vv.x; acc[1][1] += pb*vv.y;
            acc[1][2] += pb*vv.z; acc[1][3] += pb*vv.w;
        }
        __syncthreads();
    }

    // ======== write out tile ========
    {
        float* orow = outp + (size_t)(h*Sdim + qb)*Ddim;
        #pragma unroll
        for (int j = 0; j < 2; j++) {
            int q = tq + 16*j;
            float is = invs[q];
            float4 r = make_float4(acc[j][0]*is, acc[j][1]*is,
                                   acc[j][2]*is, acc[j][3]*is);
            *(float4*)&orow[q*Ddim + 4*tk] = r;
        }
    }
}

extern "C" void kernel_launch(void* const* d_in, const int* in_sizes, int n_in,
                              void* d_out, int out_size) {
    const float* Q = (const float*)d_in[0];
    const float* K = (const float*)d_in[1];
    const float* V = (const float*)d_in[2];
    float* outp = (float*)d_out;
    float* attn = outp + (size_t)Hn*Sdim*Ddim;   // tuple: (out, attn)

    const int smem_bytes = SMEM_FLOATS * (int)sizeof(float);   // ~97 KB
    cudaFuncSetAttribute(swa_kernel, cudaFuncAttributeMaxDynamicSharedMemorySize,
                         smem_bytes);

    dim3 grid(Sdim / TQ, Hn);   // (128, 16)
    swa_kernel<<<grid, 256, smem_bytes>>>(Q, K, V, outp, attn);
}

// round 3
// speedup vs baseline: 1.0010x; 1.0010x over previous
#include <cuda_runtime.h>

#define Sdim 4096
#define Ddim 64
#define WIN  256
#define Hn   16
#define TQ   32
#define CK   64
#define NCH  9
#define KBUF (CK*NCH)   /* 576 */
#define SROW 580
#define QROW 34

// SMEM floats: scores[TQ][SROW] + Qs[D][QROW] + KVs[CK][D] + invs[TQ]
#define SMEM_FLOATS (TQ*SROW + Ddim*QROW + CK*Ddim + TQ)

__global__ __launch_bounds__(256, 2)
void swa_kernel(const float* __restrict__ Q, const float* __restrict__ K,
                const float* __restrict__ V, float* __restrict__ outp,
                float* __restrict__ attn)
{
    extern __shared__ float sm[];
    float* scores = sm;                     // [TQ][SROW]
    float* Qs     = sm + TQ*SROW;           // [D][QROW]  (d-major)
    float* KVs    = Qs + Ddim*QROW;         // [CK][D] or [D][CK]
    float* invs   = KVs + CK*Ddim;          // [TQ]

    const int h    = blockIdx.y;
    const int qb   = blockIdx.x * TQ;
    const int tid  = threadIdx.x;
    const int koff = qb - WIN;              // buffer covers keys [koff, koff+576)

    // ---- Load Q tile (32x64), store transposed d-major ----
    {
        const float4* Q4 = (const float4*)(Q + (size_t)(h*Sdim + qb)*Ddim);
        #pragma unroll
        for (int i = 0; i < 2; i++) {
            int idx = tid + 256*i;      // 512 float4 total
            int q  = idx >> 4;
            int dg = idx & 15;
            float4 v = Q4[q*16 + dg];
            Qs[(4*dg+0)*QROW + q] = v.x;
            Qs[(4*dg+1)*QROW + q] = v.y;
            Qs[(4*dg+2)*QROW + q] = v.z;
            Qs[(4*dg+3)*QROW + q] = v.w;
        }
    }
    __syncthreads();

    const int tq = tid & 15;    // 16 query-pairs / 16 query-splits
    const int tk = tid >> 4;    // 16 groups of 4 keys / 4 dims

    // ======== GEMM1: scores = Q K^T * 0.125, banded mask -> -1e9 ========
    for (int c = 0; c < NCH; c++) {
        const int kc = koff + c*CK;
        const bool any = (kc < Sdim) && (kc + CK > 0);   // uniform per block
        if (any) {
            // load K chunk transposed: KVs[d][k], stride CK
            #pragma unroll
            for (int i = 0; i < 4; i++) {
                int idx = tid + 256*i;   // 1024 float4
                int kk = idx >> 4;
                int dg = idx & 15;
                int kg = kc + kk;
                float4 v = make_float4(0.f,0.f,0.f,0.f);
                if (kg >= 0 && kg < Sdim)
                    v = *(const float4*)(K + (size_t)(h*Sdim + kg)*Ddim + 4*dg);
                KVs[(4*dg+0)*CK + kk] = v.x;
                KVs[(4*dg+1)*CK + kk] = v.y;
                KVs[(4*dg+2)*CK + kk] = v.z;
                KVs[(4*dg+3)*CK + kk] = v.w;
            }
            __syncthreads();

            float acc[2][4] = {};
            #pragma unroll 8
            for (int d = 0; d < Ddim; d++) {
                float2 qv = *(const float2*)&Qs[d*QROW + 2*tq];
                float4 kv = *(const float4*)&KVs[d*CK + 4*tk];
                acc[0][0] += qv.x*kv.x; acc[0][1] += qv.x*kv.y;
                acc[0][2] += qv.x*kv.z; acc[0][3] += qv.x*kv.w;
                acc[1][0] += qv.y*kv.x; acc[1][1] += qv.y*kv.y;
                acc[1][2] += qv.y*kv.z; acc[1][3] += qv.y*kv.w;
            }
            #pragma unroll
            for (int j = 0; j < 2; j++) {
                int q  = 2*tq + j;
                int qg = qb + q;
                int k0 = kc + 4*tk;
                float4 r;
                float* rp = &r.x;
                #pragma unroll
                for (int i = 0; i < 4; i++) {
                    int kg = k0 + i;
                    bool ok = (kg >= 0) && (kg < Sdim) &&
                              ((unsigned)(kg - qg + WIN) <= 2u*WIN);
                    rp[i] = ok ? acc[j][i]*0.125f : -1e9f;
                }
                *(float4*)&scores[q*SROW + c*CK + 4*tk] = r;
            }
            __syncthreads();   // KVs reused next chunk
        } else {
            float4 mneg = make_float4(-1e9f,-1e9f,-1e9f,-1e9f);
            *(float4*)&scores[(2*tq  )*SROW + c*CK + 4*tk] = mneg;
            *(float4*)&scores[(2*tq+1)*SROW + c*CK + 4*tk] = mneg;
        }
    }
    __syncthreads();

    // ======== softmax per query row (warp handles 4 rows) ========
    {
        const int warp = tid >> 5, lane = tid & 31;
        for (int qq = 0; qq < 4; qq++) {
            int q = warp*4 + qq;
            float* row = scores + q*SROW;
            float m = -3.0e38f;
            for (int i = lane; i < KBUF; i += 32) m = fmaxf(m, row[i]);
            #pragma unroll
            for (int o = 16; o > 0; o >>= 1) m = fmaxf(m, __shfl_xor_sync(0xffffffffu, m, o));
            float ssum = 0.f;
            for (int i = lane; i < KBUF; i += 32) {
                float p = __expf(row[i] - m);   // masked -1e9 underflows to exact 0
                row[i] = p;
                ssum += p;
            }
            #pragma unroll
            for (int o = 16; o > 0; o >>= 1) ssum += __shfl_xor_sync(0xffffffffu, ssum, o);
            if (lane == 0) invs[q] = 1.0f / ssum;
        }
    }
    __syncthreads();

    // ======== write dense attn rows (zeros outside buffer/band) ========
    {
        float* arow = attn + (size_t)(h*Sdim + qb)*Sdim;
        for (int idx = tid; idx < TQ*(Sdim/4); idx += 256) {
            int q  = idx >> 10;            // Sdim/4 = 1024 groups per row
            int g  = idx & 1023;
            int k0 = g*4;
            int b  = k0 - koff;
            float4 v;
            if (b >= 0 && b < KBUF) {
                float4 p = *(float4*)&scores[q*SROW + b];
                float is = invs[q];
                v = make_float4(p.x*is, p.y*is, p.z*is, p.w*is);
            } else {
                v = make_float4(0.f,0.f,0.f,0.f);
            }
            *(float4*)&arow[(size_t)q*Sdim + k0] = v;
        }
    }

    // ======== GEMM2: out = P V (P = unnormalized exp, scale at end) ========
    float acc[2][4] = {};
    for (int c = 0; c < NCH; c++) {
        const int kc = koff + c*CK;
        if (kc >= Sdim || kc + CK <= 0) continue;   // uniform
        // load V chunk (k-major, stride D)
        #pragma unroll
        for (int i = 0; i < 4; i++) {
            int idx = tid + 256*i;
            int kk = idx >> 4;
            int dg = idx & 15;
            int kg = kc + kk;
            float4 v = make_float4(0.f,0.f,0.f,0.f);
            if (kg >= 0 && kg < Sdim)
                v = *(const float4*)(V + (size_t)(h*Sdim + kg)*Ddim + 4*dg);
            *(float4*)&KVs[kk*Ddim + 4*dg] = v;
        }
        __syncthreads();

        const int cb = c*CK;
        #pragma unroll 8
        for (int kk = 0; kk < CK; kk++) {
            float pa = scores[(tq     )*SROW + cb + kk];
            float pb = scores[(tq + 16)*SROW + cb + kk];
            float4 vv = *(const float4*)&KVs[kk*Ddim + 4*tk];
            acc[0][0] += pa*vv.x; acc[0][1] += pa*vv.y;
            acc[0][2] += pa*vv.z; acc[0][3] += pa*vv.w;
            acc[1][0] += pb*vv.x; acc[1][1] += pb*vv.y;
            acc[1][2] += pb*vv.z; acc[1][3] += pb*vv.w;
        }
        __syncthreads();
    }

    // ======== write out tile ========
    {
        float* orow = outp + (size_t)(h*Sdim + qb)*Ddim;
        #pragma unroll
        for (int j = 0; j < 2; j++) {
            int q = tq + 16*j;
            float is = invs[q];
            float4 r = make_float4(acc[j][0]*is, acc[j][1]*is,
                                   acc[j][2]*is, acc[j][3]*is);
            *(float4*)&orow[q*Ddim + 4*tk] = r;
        }
    }
}

extern "C" void kernel_launch(void* const* d_in, const int* in_sizes, int n_in,
                              void* d_out, int out_size) {
    const float* Q = (const float*)d_in[0];
    const float* K = (const float*)d_in[1];
    const float* V = (const float*)d_in[2];
    float* outp = (float*)d_out;
    float* attn = outp + (size_t)Hn*Sdim*Ddim;   // tuple: (out, attn)

    const int smem_bytes = SMEM_FLOATS * (int)sizeof(float);   // ~97 KB
    cudaFuncSetAttribute(swa_kernel, cudaFuncAttributeMaxDynamicSharedMemorySize,
                         smem_bytes);

    dim3 grid(Sdim / TQ, Hn);   // (128, 16)
    swa_kernel<<<grid, 256, smem_bytes>>>(Q, K, V, outp, attn);
}